// round 10
// baseline (speedup 1.0000x reference)
#include <cuda_runtime.h>
#include <cstdint>
#include <math.h>

// Problem dims
#define T_SEQ 512
#define BATCH 8
#define HID   512
#define EMB   256
#define VOCAB 32000
#define M_TOT (BATCH*T_SEQ)   // 4096
#define G4H   (4*HID)         // 2048

typedef unsigned long long u64;

// ---------------- scratch (device globals; no allocation allowed) -----------
__device__ float g_x0 [M_TOT*EMB];      // gathered embeddings
__device__ float g_xg [M_TOT*G4H];      // layer0 input-gate contributions
__device__ float g_hs1[M_TOT*HID];      // layer1 outputs (FC input)
__device__ float g_h0 [2][HID*BATCH];   // double-buffered h, layout [n][b]
__device__ float g_h1 [2][HID*BATCH];
__device__ float g_c  [2][HID*BATCH];   // cell state per layer, layout [n][b]

// ---------------- embedding gather ------------------------------------------
__global__ void gather_kernel(const int* __restrict__ ids,
                              const float* __restrict__ emb) {
    int m  = blockIdx.x;
    int id = ids[m];
    const float4* s = (const float4*)(emb + (size_t)id * EMB);
    float4*       d = (float4*)(g_x0 + (size_t)m * EMB);
    d[threadIdx.x] = s[threadIdx.x];
}

// ---------------- state reset (before the recurrence) -----------------------
__global__ void reset_kernel() {
    int i = blockIdx.x * blockDim.x + threadIdx.x;
    int n = HID * BATCH;
    if (i < n) {
        g_h0[0][i] = 0.f; g_h0[1][i] = 0.f;
        g_h1[0][i] = 0.f; g_h1[1][i] = 0.f;
        g_c [0][i] = 0.f; g_c [1][i] = 0.f;
    }
}

// ---------------- tf32 mma GEMM: C[m][n] = sum_k A[m][k]*B[n][k] + bias -----
__device__ __forceinline__ float f2tf32(float x) {
    float r;
    asm("cvt.rna.tf32.f32 %0, %1;" : "=f"(r) : "f"(x));
    return r;
}

__global__ void __launch_bounds__(256)
gemm_tf32_kernel(const float* __restrict__ A, const float* __restrict__ B,
                 const float* __restrict__ bias1, const float* __restrict__ bias2,
                 float* __restrict__ C, int M, int N, int K)
{
    __shared__ float As[128][36];
    __shared__ float Bs[128][36];

    int tid  = threadIdx.x;
    int warp = tid >> 5, lane = tid & 31;
    int wm   = warp >> 2, wn = warp & 3;
    int grp  = lane >> 2, tig = lane & 3;

    int mBase = blockIdx.y << 7;
    int nBase = blockIdx.x << 7;

    float acc[4][4][4];
    #pragma unroll
    for (int a = 0; a < 4; a++)
        #pragma unroll
        for (int b = 0; b < 4; b++)
            #pragma unroll
            for (int c = 0; c < 4; c++) acc[a][b][c] = 0.f;

    for (int k0 = 0; k0 < K; k0 += 32) {
        #pragma unroll
        for (int i = 0; i < 4; i++) {
            int f  = tid + (i << 8);
            int m  = f >> 3;
            int k4 = (f & 7) << 2;
            float4 va = *(const float4*)(A + (size_t)(mBase + m) * K + k0 + k4);
            *(float4*)&As[m][k4] = make_float4(f2tf32(va.x), f2tf32(va.y),
                                               f2tf32(va.z), f2tf32(va.w));
            float4 vb = *(const float4*)(B + (size_t)(nBase + m) * K + k0 + k4);
            *(float4*)&Bs[m][k4] = make_float4(f2tf32(vb.x), f2tf32(vb.y),
                                               f2tf32(vb.z), f2tf32(vb.w));
        }
        __syncthreads();

        #pragma unroll
        for (int kk = 0; kk < 32; kk += 8) {
            uint32_t af[4][4], bf[4][2];
            #pragma unroll
            for (int mi = 0; mi < 4; mi++) {
                int r = (wm << 6) + (mi << 4);
                af[mi][0] = __float_as_uint(As[r + grp    ][kk + tig    ]);
                af[mi][1] = __float_as_uint(As[r + grp + 8][kk + tig    ]);
                af[mi][2] = __float_as_uint(As[r + grp    ][kk + tig + 4]);
                af[mi][3] = __float_as_uint(As[r + grp + 8][kk + tig + 4]);
            }
            #pragma unroll
            for (int ni = 0; ni < 4; ni++) {
                int cN = (wn << 5) + (ni << 3);
                bf[ni][0] = __float_as_uint(Bs[cN + grp][kk + tig    ]);
                bf[ni][1] = __float_as_uint(Bs[cN + grp][kk + tig + 4]);
            }
            #pragma unroll
            for (int mi = 0; mi < 4; mi++)
                #pragma unroll
                for (int ni = 0; ni < 4; ni++)
                    asm volatile(
                        "mma.sync.aligned.m16n8k8.row.col.f32.tf32.tf32.f32 "
                        "{%0,%1,%2,%3}, {%4,%5,%6,%7}, {%8,%9}, {%0,%1,%2,%3};"
                        : "+f"(acc[mi][ni][0]), "+f"(acc[mi][ni][1]),
                          "+f"(acc[mi][ni][2]), "+f"(acc[mi][ni][3])
                        : "r"(af[mi][0]), "r"(af[mi][1]),
                          "r"(af[mi][2]), "r"(af[mi][3]),
                          "r"(bf[ni][0]), "r"(bf[ni][1]));
        }
        __syncthreads();
    }

    #pragma unroll
    for (int mi = 0; mi < 4; mi++) {
        int mrow = mBase + (wm << 6) + (mi << 4) + grp;
        #pragma unroll
        for (int ni = 0; ni < 4; ni++) {
            int nc = nBase + (wn << 5) + (ni << 3) + (tig << 1);
            float b0 = bias1[nc], b1 = bias1[nc + 1];
            if (bias2) { b0 += bias2[nc]; b1 += bias2[nc + 1]; }
            float2 v0 = make_float2(acc[mi][ni][0] + b0, acc[mi][ni][1] + b1);
            float2 v1 = make_float2(acc[mi][ni][2] + b0, acc[mi][ni][3] + b1);
            *(float2*)(C + (size_t)mrow       * N + nc) = v0;
            *(float2*)(C + (size_t)(mrow + 8) * N + nc) = v1;
        }
    }
}

// ---------------- per-timestep LSTM step (wavefront-fused layers) -----------
// Launch l = 0..512. CTAs 0..127: layer0 step t=l. CTAs 128..255: layer1 t=l-1.
// CTA owns 4 hidden units (16 gate rows). Thread tile: 2 rows x 4 batches x
// k-split 8, packed f32x2 FMAs, k-partials reduced through smem.
#define WST0 516    // 512 + 4 pad floats (row stride, 16B-aligned)
#define WST1 1036   // 1024 + 12 pad floats (L1: [Whh1|Wih1] and [h1|h0] concat)

#define FMA2(a, x, y) \
    asm("fma.rn.f32x2 %0, %1, %2, %0;" : "+l"(a) : "l"(x), "l"(y))

__global__ void __launch_bounds__(128)
lstm_step_kernel(int l,
                 const float* __restrict__ Whh0, const float* __restrict__ xg,
                 const float* __restrict__ Whh1, const float* __restrict__ Wih1,
                 const float* __restrict__ bi1,  const float* __restrict__ bh1,
                 float* __restrict__ hs1)
{
    extern __shared__ float sm[];
    int tid  = threadIdx.x;
    bool isL1 = blockIdx.x >= 128;
    int cta  = isL1 ? blockIdx.x - 128 : blockIdx.x;
    int base = cta << 2;                 // first owned hidden unit
    int rp   = (l + 1) & 1;              // read parity
    int wpar = l & 1;                    // write parity

    // dot-phase thread tile: rows {2rp2, 2rp2+1}, batches {4bh..4bh+3}, ksplit
    int rp2 = tid >> 4;                  // row pair 0..7
    int bh  = (tid >> 3) & 1;            // batch half 0..1
    int ks  = tid & 7;                   // k split 0..7

    if (!isL1) {
        if (l >= T_SEQ) return;
        float* Ws = sm;                        // 16 x WST0
        float* Hb = sm + 16 * WST0;            //  8 x WST0
        float* Pt = sm + 24 * WST0;            // 128 x 9 partials
        float* Gs = Pt + 128 * 9;              // 128 gate pre-activations

        // stage W_hh0 slice: 16 rows x 512 = 2048 float4
        #pragma unroll 4
        for (int i = tid; i < 2048; i += 128) {
            int r = i >> 7, c4 = (i & 127) << 2;
            int g = r >> 2, u = r & 3;
            float4 v = *(const float4*)(Whh0 +
                        (size_t)((g << 9) + base + u) * HID + c4);
            *(float4*)(Ws + r * WST0 + c4) = v;
        }
        // stage h0_{t-1} transposed: global [k][b] -> smem [b][k]
        const float* hsrc = g_h0[rp];
        #pragma unroll 8
        for (int i = tid; i < HID * BATCH; i += 128) {
            int k = i >> 3, b = i & 7;
            Hb[b * WST0 + k] = hsrc[i];
        }
        __syncthreads();

        const ulonglong2* w0 = (const ulonglong2*)(Ws + (2*rp2  ) * WST0) + (ks << 4);
        const ulonglong2* w1 = (const ulonglong2*)(Ws + (2*rp2+1) * WST0) + (ks << 4);
        const ulonglong2* hp[4];
        #pragma unroll
        for (int j = 0; j < 4; j++)
            hp[j] = (const ulonglong2*)(Hb + ((bh << 2) + j) * WST0) + (ks << 4);

        u64 acc[2][4];
        #pragma unroll
        for (int i = 0; i < 2; i++)
            #pragma unroll
            for (int j = 0; j < 4; j++) acc[i][j] = 0ull;

        #pragma unroll
        for (int c = 0; c < 16; c++) {
            ulonglong2 wa = w0[c], wb = w1[c];
            #pragma unroll
            for (int j = 0; j < 4; j++) {
                ulonglong2 hv = hp[j][c];
                FMA2(acc[0][j], wa.x, hv.x); FMA2(acc[0][j], wa.y, hv.y);
                FMA2(acc[1][j], wb.x, hv.x); FMA2(acc[1][j], wb.y, hv.y);
            }
        }
        #pragma unroll
        for (int i = 0; i < 2; i++)
            #pragma unroll
            for (int j = 0; j < 4; j++) {
                float lo, hi;
                asm("mov.b64 {%0,%1}, %2;" : "=f"(lo), "=f"(hi) : "l"(acc[i][j]));
                int slot = ((2*rp2 + i) << 3) + (bh << 2) + j;
                Pt[slot * 9 + ks] = lo + hi;
            }
        __syncthreads();

        // reduce k-partials + add xg contribution
        {
            int slot = tid;                    // 0..127 = row*8 + b
            int r = slot >> 3, b = slot & 7;
            int g = r >> 2, u = r & 3;
            float s = 0.f;
            #pragma unroll
            for (int k = 0; k < 8; k++) s += Pt[slot * 9 + k];
            float xv = __ldg(xg + (size_t)((b << 9) + l) * G4H + (g << 9) + base + u);
            Gs[slot] = s + xv;
        }
        __syncthreads();

        if (tid < 32) {
            int uu = tid >> 3, bb = tid & 7;
            int nn = base + uu;
            int id = (uu << 3) + bb;
            float iv = Gs[id], fv = Gs[32 + id];
            float gv = Gs[64 + id], ov = Gs[96 + id];
            float i_ = 1.f / (1.f + expf(-iv));
            float f_ = 1.f / (1.f + expf(-fv));
            float gg = tanhf(gv);
            float o_ = 1.f / (1.f + expf(-ov));
            float c  = f_ * g_c[0][(nn << 3) + bb] + i_ * gg;
            g_c[0][(nn << 3) + bb] = c;
            g_h0[wpar][(nn << 3) + bb] = o_ * tanhf(c);
        }
    } else {
        if (l < 1) return;
        int t = l - 1;
        float* Ws = sm;                        // 16 x WST1  ([Whh1 | Wih1])
        float* Hb = sm + 16 * WST1;            //  8 x WST1  ([h1_prev | h0_t])
        float* Pt = sm + 24 * WST1;            // 128 x 9
        float* Gs = Pt + 128 * 9;              // 128

        // stage combined weights: 16 rows x 1024 = 4096 float4
        #pragma unroll 4
        for (int i = tid; i < 4096; i += 128) {
            int r = i >> 8, c4 = (i & 255) << 2;
            int g = r >> 2, u = r & 3;
            const float* src = (c4 < 512) ? Whh1 : Wih1;
            int col = (c4 < 512) ? c4 : c4 - 512;
            float4 v = *(const float4*)(src +
                        (size_t)((g << 9) + base + u) * HID + col);
            *(float4*)(Ws + r * WST1 + c4) = v;
        }
        // stage [h1_prev | h0_t] transposed
        const float* h1src = g_h1[rp];
        const float* h0src = g_h0[rp];         // h0_t written at launch l-1
        #pragma unroll 8
        for (int i = tid; i < 2 * HID * BATCH; i += 128) {
            int half = i >> 12;                // 0: h1, 1: h0
            int j = i & 4095;
            int k = j >> 3, b = j & 7;
            Hb[b * WST1 + (half << 9) + k] = half ? h0src[j] : h1src[j];
        }
        __syncthreads();

        const ulonglong2* w0 = (const ulonglong2*)(Ws + (2*rp2  ) * WST1) + (ks << 5);
        const ulonglong2* w1 = (const ulonglong2*)(Ws + (2*rp2+1) * WST1) + (ks << 5);
        const ulonglong2* hp[4];
        #pragma unroll
        for (int j = 0; j < 4; j++)
            hp[j] = (const ulonglong2*)(Hb + ((bh << 2) + j) * WST1) + (ks << 5);

        u64 acc[2][4];
        #pragma unroll
        for (int i = 0; i < 2; i++)
            #pragma unroll
            for (int j = 0; j < 4; j++) acc[i][j] = 0ull;

        #pragma unroll
        for (int c = 0; c < 32; c++) {
            ulonglong2 wa = w0[c], wb = w1[c];
            #pragma unroll
            for (int j = 0; j < 4; j++) {
                ulonglong2 hv = hp[j][c];
                FMA2(acc[0][j], wa.x, hv.x); FMA2(acc[0][j], wa.y, hv.y);
                FMA2(acc[1][j], wb.x, hv.x); FMA2(acc[1][j], wb.y, hv.y);
            }
        }
        #pragma unroll
        for (int i = 0; i < 2; i++)
            #pragma unroll
            for (int j = 0; j < 4; j++) {
                float lo, hi;
                asm("mov.b64 {%0,%1}, %2;" : "=f"(lo), "=f"(hi) : "l"(acc[i][j]));
                int slot = ((2*rp2 + i) << 3) + (bh << 2) + j;
                Pt[slot * 9 + ks] = lo + hi;
            }
        __syncthreads();

        {
            int slot = tid;
            int r = slot >> 3;
            int g = r >> 2, u = r & 3;
            float s = 0.f;
            #pragma unroll
            for (int k = 0; k < 8; k++) s += Pt[slot * 9 + k];
            float bias = __ldg(bi1 + (g << 9) + base + u)
                       + __ldg(bh1 + (g << 9) + base + u);
            Gs[slot] = s + bias;
        }
        __syncthreads();

        if (tid < 32) {
            int uu = tid >> 3, bb = tid & 7;
            int nn = base + uu;
            int id = (uu << 3) + bb;
            float iv = Gs[id], fv = Gs[32 + id];
            float gv = Gs[64 + id], ov = Gs[96 + id];
            float i_ = 1.f / (1.f + expf(-iv));
            float f_ = 1.f / (1.f + expf(-fv));
            float gg = tanhf(gv);
            float o_ = 1.f / (1.f + expf(-ov));
            float c  = f_ * g_c[1][(nn << 3) + bb] + i_ * gg;
            g_c[1][(nn << 3) + bb] = c;
            float h  = o_ * tanhf(c);
            g_h1[wpar][(nn << 3) + bb] = h;
            hs1[(size_t)((bb << 9) + t) * HID + nn] = h;
        }
    }
}

// ---------------- launch -----------------------------------------------------
extern "C" void kernel_launch(void* const* d_in, const int* in_sizes, int n_in,
                              void* d_out, int out_size)
{
    (void)in_sizes; (void)n_in; (void)out_size;
    const int*   ids   = (const int*)d_in[0];
    const float* emb   = (const float*)d_in[1];
    const float* W_ih0 = (const float*)d_in[2];
    const float* W_hh0 = (const float*)d_in[3];
    const float* b_ih0 = (const float*)d_in[4];
    const float* b_hh0 = (const float*)d_in[5];
    const float* W_ih1 = (const float*)d_in[6];
    const float* W_hh1 = (const float*)d_in[7];
    const float* b_ih1 = (const float*)d_in[8];
    const float* b_hh1 = (const float*)d_in[9];
    const float* W_fc  = (const float*)d_in[10];
    const float* b_fc  = (const float*)d_in[11];
    float* out = (float*)d_out;

    float *x0, *xgp, *hs1;
    cudaGetSymbolAddress((void**)&x0,  g_x0);
    cudaGetSymbolAddress((void**)&xgp, g_xg);
    cudaGetSymbolAddress((void**)&hs1, g_hs1);

    // dynamic smem sized for the L1 branch: 24*WST1 + 128*9 + 128 floats
    const int step_smem = (24 * WST1 + 128 * 9 + 128) * (int)sizeof(float); // 104576
    cudaFuncSetAttribute(lstm_step_kernel,
                         cudaFuncAttributeMaxDynamicSharedMemorySize, step_smem);

    // 1) gather embeddings
    gather_kernel<<<M_TOT, EMB / 4>>>(ids, emb);

    // 2) xg = x0 @ W_ih0^T + b_ih0 + b_hh0     [4096 x 2048], K=256
    gemm_tf32_kernel<<<dim3(G4H / 128, M_TOT / 128), 256>>>(
        x0, W_ih0, b_ih0, b_hh0, xgp, M_TOT, G4H, EMB);

    // 3) zero h/c state
    reset_kernel<<<(HID * BATCH + 255) / 256, 256>>>();

    // 4) recurrence: one launch per wavefront step
    for (int l = 0; l <= T_SEQ; l++) {
        lstm_step_kernel<<<256, 128, step_smem>>>(
            l, W_hh0, xgp, W_hh1, W_ih1, b_ih1, b_hh1, hs1);
    }

    // 5) logits = hs1 @ W_fc^T + b_fc          [4096 x 32000], K=512
    gemm_tf32_kernel<<<dim3(VOCAB / 128, M_TOT / 128), 256>>>(
        hs1, W_fc, b_fc, nullptr, out, M_TOT, VOCAB, HID);
}

// round 11
// speedup vs baseline: 3.4458x; 3.4458x over previous
#include <cuda_runtime.h>
#include <cstdint>
#include <math.h>

// Problem dims
#define T_SEQ 512
#define BATCH 8
#define HID   512
#define EMB   256
#define VOCAB 32000
#define M_TOT (BATCH*T_SEQ)   // 4096
#define G4H   (4*HID)         // 2048

typedef unsigned long long u64;

// ---------------- scratch (device globals; no allocation allowed) -----------
__device__ float    g_x0 [M_TOT*EMB];      // gathered embeddings
__device__ float    g_xg [M_TOT*G4H];      // layer0 input-gate contributions
__device__ float    g_hs1[M_TOT*HID];      // layer1 outputs (FC input)
__device__ float    g_h0 [2][HID*BATCH];   // double-buffered h0, layout [n][b]
__device__ float    g_h1 [2][HID*BATCH];   // double-buffered h1
__device__ unsigned g_bar;                 // monotonic wavefront barrier
__device__ unsigned g_abort;               // safety abort flag

// ---------------- embedding gather ------------------------------------------
__global__ void gather_kernel(const int* __restrict__ ids,
                              const float* __restrict__ emb) {
    int m  = blockIdx.x;
    int id = ids[m];
    const float4* s = (const float4*)(emb + (size_t)id * EMB);
    float4*       d = (float4*)(g_x0 + (size_t)m * EMB);
    d[threadIdx.x] = s[threadIdx.x];
}

// ---------------- barrier / h-buffer reset (before the recurrence) ----------
__global__ void reset_kernel() {
    int i = blockIdx.x * blockDim.x + threadIdx.x;
    if (i == 0) { g_bar = 0u; g_abort = 0u; }
    if (i < HID * BATCH) {
        g_h0[0][i] = 0.f; g_h0[1][i] = 0.f;
        g_h1[0][i] = 0.f; g_h1[1][i] = 0.f;
    }
}

// ---------------- tf32 mma GEMM: C[m][n] = sum_k A[m][k]*B[n][k] + bias -----
__device__ __forceinline__ float f2tf32(float x) {
    float r;
    asm("cvt.rna.tf32.f32 %0, %1;" : "=f"(r) : "f"(x));
    return r;
}

__global__ void __launch_bounds__(256)
gemm_tf32_kernel(const float* __restrict__ A, const float* __restrict__ B,
                 const float* __restrict__ bias1, const float* __restrict__ bias2,
                 float* __restrict__ C, int M, int N, int K)
{
    __shared__ float As[128][36];
    __shared__ float Bs[128][36];

    int tid  = threadIdx.x;
    int warp = tid >> 5, lane = tid & 31;
    int wm   = warp >> 2, wn = warp & 3;
    int grp  = lane >> 2, tig = lane & 3;

    int mBase = blockIdx.y << 7;
    int nBase = blockIdx.x << 7;

    float acc[4][4][4];
    #pragma unroll
    for (int a = 0; a < 4; a++)
        #pragma unroll
        for (int b = 0; b < 4; b++)
            #pragma unroll
            for (int c = 0; c < 4; c++) acc[a][b][c] = 0.f;

    for (int k0 = 0; k0 < K; k0 += 32) {
        #pragma unroll
        for (int i = 0; i < 4; i++) {
            int f  = tid + (i << 8);
            int m  = f >> 3;
            int k4 = (f & 7) << 2;
            float4 va = *(const float4*)(A + (size_t)(mBase + m) * K + k0 + k4);
            *(float4*)&As[m][k4] = make_float4(f2tf32(va.x), f2tf32(va.y),
                                               f2tf32(va.z), f2tf32(va.w));
            float4 vb = *(const float4*)(B + (size_t)(nBase + m) * K + k0 + k4);
            *(float4*)&Bs[m][k4] = make_float4(f2tf32(vb.x), f2tf32(vb.y),
                                               f2tf32(vb.z), f2tf32(vb.w));
        }
        __syncthreads();

        #pragma unroll
        for (int kk = 0; kk < 32; kk += 8) {
            uint32_t af[4][4], bf[4][2];
            #pragma unroll
            for (int mi = 0; mi < 4; mi++) {
                int r = (wm << 6) + (mi << 4);
                af[mi][0] = __float_as_uint(As[r + grp    ][kk + tig    ]);
                af[mi][1] = __float_as_uint(As[r + grp + 8][kk + tig    ]);
                af[mi][2] = __float_as_uint(As[r + grp    ][kk + tig + 4]);
                af[mi][3] = __float_as_uint(As[r + grp + 8][kk + tig + 4]);
            }
            #pragma unroll
            for (int ni = 0; ni < 4; ni++) {
                int cN = (wn << 5) + (ni << 3);
                bf[ni][0] = __float_as_uint(Bs[cN + grp][kk + tig    ]);
                bf[ni][1] = __float_as_uint(Bs[cN + grp][kk + tig + 4]);
            }
            #pragma unroll
            for (int mi = 0; mi < 4; mi++)
                #pragma unroll
                for (int ni = 0; ni < 4; ni++)
                    asm volatile(
                        "mma.sync.aligned.m16n8k8.row.col.f32.tf32.tf32.f32 "
                        "{%0,%1,%2,%3}, {%4,%5,%6,%7}, {%8,%9}, {%0,%1,%2,%3};"
                        : "+f"(acc[mi][ni][0]), "+f"(acc[mi][ni][1]),
                          "+f"(acc[mi][ni][2]), "+f"(acc[mi][ni][3])
                        : "r"(af[mi][0]), "r"(af[mi][1]),
                          "r"(af[mi][2]), "r"(af[mi][3]),
                          "r"(bf[ni][0]), "r"(bf[ni][1]));
        }
        __syncthreads();
    }

    #pragma unroll
    for (int mi = 0; mi < 4; mi++) {
        int mrow = mBase + (wm << 6) + (mi << 4) + grp;
        #pragma unroll
        for (int ni = 0; ni < 4; ni++) {
            int nc = nBase + (wn << 5) + (ni << 3) + (tig << 1);
            float b0 = bias1[nc], b1 = bias1[nc + 1];
            if (bias2) { b0 += bias2[nc]; b1 += bias2[nc + 1]; }
            float2 v0 = make_float2(acc[mi][ni][0] + b0, acc[mi][ni][1] + b1);
            float2 v1 = make_float2(acc[mi][ni][2] + b0, acc[mi][ni][3] + b1);
            *(float2*)(C + (size_t)mrow       * N + nc) = v0;
            *(float2*)(C + (size_t)(mrow + 8) * N + nc) = v1;
        }
    }
}

// ---------------- persistent wavefront LSTM ---------------------------------
// ONE launch, 128 CTAs, all co-resident (1 CTA/SM at 176KB smem, 128 <= 148).
// CTAs 0..63: layer0 (8 hidden units each). CTAs 64..127: layer1.
// Wavefront l = 0..512: layer0 computes t=l (l<512), layer1 computes t=l-1
// (l>=1). W lives in SMEM for the whole sequence. h exchanged through
// double-buffered globals + monotonic barrier with bounded spin + abort.
//
// Dot mapping: lane = gate row (0..31), warp = k-chunk slice; h is a warp
// broadcast, w rows are read exactly once per step. 8 batch accumulators in
// packed f32x2; cross-warp k-partials reduced via smem.
#define NCTA_TOT 128
#define WST0 516    // floats; row stride layer0 (512 + 4 pad)
#define WST1 1036   // floats; row stride layer1 concat [Whh1|Wih1] (1024 + 12)

#define FMA2(a, x, y) \
    asm("fma.rn.f32x2 %0, %1, %2, %0;" : "+l"(a) : "l"(x), "l"(y))

__global__ void __launch_bounds__(256)
lstm_persist_kernel(const float* __restrict__ Whh0, const float* __restrict__ xg,
                    const float* __restrict__ Whh1, const float* __restrict__ Wih1,
                    const float* __restrict__ bi1,  const float* __restrict__ bh1,
                    float* __restrict__ hs1)
{
    extern __shared__ float sm[];
    __shared__ int s_flag;
    int tid  = threadIdx.x;
    bool isL1 = blockIdx.x >= 64;
    int base = (isL1 ? blockIdx.x - 64 : blockIdx.x) << 3;   // first owned unit

    const int WST = isL1 ? WST1 : WST0;
    float* Ws = sm;                    // 32 rows x WST
    float* Hb = sm + 32 * WST;         //  8 x WST   (h inputs, [b][k])
    float* Pt = Hb + 8 * WST;          // 256 x 9 k-partials
    float* Gs = Pt + 256 * 9;          // 256 gate pre-activations
    float* Cs = Gs + 256;              // 64 cell states

    // ---- one-time staging: W slice (rows = g*8+u for owned units) ----
    if (!isL1) {
        #pragma unroll 4
        for (int i = tid; i < 4096; i += 256) {        // 32 rows x 128 float4
            int r = i >> 7, c4 = (i & 127) << 2;
            int g = r >> 3, u = r & 7;
            *(float4*)(Ws + r * WST0 + c4) =
                *(const float4*)(Whh0 + (size_t)((g << 9) + base + u) * HID + c4);
        }
    } else {
        #pragma unroll 4
        for (int i = tid; i < 8192; i += 256) {        // 32 rows x 256 float4
            int r = i >> 8, c4 = (i & 255) << 2;
            int g = r >> 3, u = r & 7;
            const float* src = (c4 < 512) ? Whh1 : Wih1;
            int col = (c4 < 512) ? c4 : c4 - 512;
            *(float4*)(Ws + r * WST1 + c4) =
                *(const float4*)(src + (size_t)((g << 9) + base + u) * HID + col);
        }
    }
    for (int i = tid; i < 8 * WST; i += 256) Hb[i] = 0.f;   // h_{-1} = 0
    if (tid < 64) Cs[tid] = 0.f;
    if (tid == 0) s_flag = 0;

    // reduce-phase constants: slot tid = (row, b); row = g*8+u
    int rrow = tid >> 3, rb = tid & 7;
    int rgrow = ((rrow >> 3) << 9) + base + (rrow & 7);     // global gate row
    float rbias = isL1 ? (__ldg(bi1 + rgrow) + __ldg(bh1 + rgrow)) : 0.f;
    __syncthreads();

    // dot-phase mapping: lane = row, warp = k slice
    int w    = tid >> 5, lane = tid & 31;
    int ncw  = isL1 ? 32 : 16;                 // 16B chunks per warp
    int cb   = w * ncw;                        // starting chunk
    const ulonglong2* wp = (const ulonglong2*)(Ws + lane * WST) + cb;

    unsigned* barp = &g_bar;
    volatile unsigned* abtp = (volatile unsigned*)&g_abort;

    for (int l = 0; l <= T_SEQ; l++) {
        int wpar   = l & 1;
        bool active = isL1 ? (l >= 1) : (l < T_SEQ);
        int t = isL1 ? (l - 1) : l;

        float xv = 0.f;
        if (!isL1 && active)               // issue early; hidden under the dot
            xv = __ldg(xg + (size_t)((rb << 9) + t) * G4H + rgrow);

        if (active) {
            u64 acc[8];
            #pragma unroll
            for (int b = 0; b < 8; b++) acc[b] = 0ull;

            const ulonglong2* h0p = (const ulonglong2*)(Hb + 0 * WST) + cb;
            const ulonglong2* h1p = (const ulonglong2*)(Hb + 1 * WST) + cb;
            const ulonglong2* h2p = (const ulonglong2*)(Hb + 2 * WST) + cb;
            const ulonglong2* h3p = (const ulonglong2*)(Hb + 3 * WST) + cb;
            const ulonglong2* h4p = (const ulonglong2*)(Hb + 4 * WST) + cb;
            const ulonglong2* h5p = (const ulonglong2*)(Hb + 5 * WST) + cb;
            const ulonglong2* h6p = (const ulonglong2*)(Hb + 6 * WST) + cb;
            const ulonglong2* h7p = (const ulonglong2*)(Hb + 7 * WST) + cb;

            #pragma unroll 4
            for (int c = 0; c < ncw; c++) {
                ulonglong2 wv = wp[c];
                ulonglong2 h;
                h = h0p[c]; FMA2(acc[0], wv.x, h.x); FMA2(acc[0], wv.y, h.y);
                h = h1p[c]; FMA2(acc[1], wv.x, h.x); FMA2(acc[1], wv.y, h.y);
                h = h2p[c]; FMA2(acc[2], wv.x, h.x); FMA2(acc[2], wv.y, h.y);
                h = h3p[c]; FMA2(acc[3], wv.x, h.x); FMA2(acc[3], wv.y, h.y);
                h = h4p[c]; FMA2(acc[4], wv.x, h.x); FMA2(acc[4], wv.y, h.y);
                h = h5p[c]; FMA2(acc[5], wv.x, h.x); FMA2(acc[5], wv.y, h.y);
                h = h6p[c]; FMA2(acc[6], wv.x, h.x); FMA2(acc[6], wv.y, h.y);
                h = h7p[c]; FMA2(acc[7], wv.x, h.x); FMA2(acc[7], wv.y, h.y);
            }
            #pragma unroll
            for (int b = 0; b < 8; b++) {
                float lo, hi;
                asm("mov.b64 {%0,%1}, %2;" : "=f"(lo), "=f"(hi) : "l"(acc[b]));
                Pt[((lane << 3) + b) * 9 + w] = lo + hi;
            }
        }
        __syncthreads();

        if (active) {                       // reduce k-partials, add bias/xg
            float s = 0.f;
            #pragma unroll
            for (int k = 0; k < 8; k++) s += Pt[tid * 9 + k];
            Gs[tid] = s + (isL1 ? rbias : xv);
        }
        __syncthreads();

        if (active && tid < 64) {           // activations + publish h
            int u = tid >> 3, b = tid & 7;
            int id = (u << 3) + b;
            float iv = Gs[id],       fv = Gs[64 + id];
            float gv = Gs[128 + id], ov = Gs[192 + id];
            float i_ = 1.f / (1.f + expf(-iv));
            float f_ = 1.f / (1.f + expf(-fv));
            float gg = tanhf(gv);
            float o_ = 1.f / (1.f + expf(-ov));
            float c  = f_ * Cs[id] + i_ * gg;
            Cs[id]   = c;
            float h  = o_ * tanhf(c);
            int n = base + u;
            if (!isL1) {
                g_h0[wpar][(n << 3) + b] = h;
            } else {
                g_h1[wpar][(n << 3) + b] = h;
                hs1[(size_t)((b << 9) + t) * HID + n] = h;
            }
        }
        __threadfence();                    // publish before signaling
        __syncthreads();

        if (tid == 0) {                     // bounded-spin wavefront barrier
            atomicAdd(barp, 1u);
            unsigned target = (unsigned)NCTA_TOT * (unsigned)(l + 1);
            int ab = 0;
            long it = 0;
            for (;;) {
                unsigned v;
                asm volatile("ld.volatile.global.u32 %0, [%1];"
                             : "=r"(v) : "l"(barp));
                if (v >= target) break;
                if (*abtp != 0u) { ab = 1; break; }
                if (++it > 4000000) { atomicExch(&g_abort, 1u); ab = 1; break; }
                __nanosleep(64);
            }
            s_flag = ab;
        }
        __syncthreads();
        if (s_flag) return;                 // hang-proof: give up, never spin forever
        __threadfence();                    // acquire + L1D invalidate

        // refresh Hb from the freshly written state (parity wpar)
        if (!isL1) {
            const float* src = g_h0[wpar];
            #pragma unroll 4
            for (int i = tid; i < HID * BATCH; i += 256) {
                int k = i >> 3, b = i & 7;
                Hb[b * WST0 + k] = __ldcg(src + i);
            }
        } else {
            const float* h1src = g_h1[wpar];
            const float* h0src = g_h0[wpar];
            #pragma unroll 4
            for (int i = tid; i < 2 * HID * BATCH; i += 256) {
                int half = i >> 12;         // 0: h1 -> cols [0,512), 1: h0 -> [512,1024)
                int j = i & 4095;
                int k = j >> 3, b = j & 7;
                Hb[b * WST1 + (half << 9) + k] =
                    __ldcg((half ? h0src : h1src) + j);
            }
        }
        __syncthreads();
    }
}

// ---------------- launch -----------------------------------------------------
extern "C" void kernel_launch(void* const* d_in, const int* in_sizes, int n_in,
                              void* d_out, int out_size)
{
    (void)in_sizes; (void)n_in; (void)out_size;
    const int*   ids   = (const int*)d_in[0];
    const float* emb   = (const float*)d_in[1];
    const float* W_ih0 = (const float*)d_in[2];
    const float* W_hh0 = (const float*)d_in[3];
    const float* b_ih0 = (const float*)d_in[4];
    const float* b_hh0 = (const float*)d_in[5];
    const float* W_ih1 = (const float*)d_in[6];
    const float* W_hh1 = (const float*)d_in[7];
    const float* b_ih1 = (const float*)d_in[8];
    const float* b_hh1 = (const float*)d_in[9];
    const float* W_fc  = (const float*)d_in[10];
    const float* b_fc  = (const float*)d_in[11];
    float* out = (float*)d_out;

    float *x0, *xgp, *hs1;
    cudaGetSymbolAddress((void**)&x0,  g_x0);
    cudaGetSymbolAddress((void**)&xgp, g_xg);
    cudaGetSymbolAddress((void**)&hs1, g_hs1);

    // dynamic smem sized for the L1 branch:
    // 32*WST1 + 8*WST1 + 256*9 + 256 + 64 floats
    const int per_smem = (40 * WST1 + 256 * 9 + 256 + 64) * (int)sizeof(float); // 176256
    cudaFuncSetAttribute(lstm_persist_kernel,
                         cudaFuncAttributeMaxDynamicSharedMemorySize, per_smem);

    // 1) gather embeddings
    gather_kernel<<<M_TOT, EMB / 4>>>(ids, emb);

    // 2) xg = x0 @ W_ih0^T + b_ih0 + b_hh0     [4096 x 2048], K=256
    gemm_tf32_kernel<<<dim3(G4H / 128, M_TOT / 128), 256>>>(
        x0, W_ih0, b_ih0, b_hh0, xgp, M_TOT, G4H, EMB);

    // 3) reset barrier + h buffers
    reset_kernel<<<(HID * BATCH + 255) / 256, 256>>>();

    // 4) both LSTM layers in ONE persistent wavefront launch
    lstm_persist_kernel<<<NCTA_TOT, 256, per_smem>>>(
        W_hh0, xgp, W_hh1, W_ih1, b_ih1, b_hh1, hs1);

    // 5) logits = hs1 @ W_fc^T + b_fc          [4096 x 32000], K=512
    gemm_tf32_kernel<<<dim3(VOCAB / 128, M_TOT / 128), 256>>>(
        hs1, W_fc, b_fc, nullptr, out, M_TOT, VOCAB, HID);
}